// round 4
// baseline (speedup 1.0000x reference)
#include <cuda_runtime.h>

#define NPTS 16384
#define KSUB 16
#define WD   256
#define TWF  0.2f
#define PI_F 3.14159265358979f
#define AS   260   // padded activation row stride (floats)

// smem: A(64*AS) + C(64*AS) + Wtile(32*256) + xn(128) + wn(64) + idx(64)
#define SMEM_FLOATS (64*AS*2 + 32*256 + 128 + 64 + 64)
#define SMEM_BYTES  (SMEM_FLOATS * 4)

__device__ int   g_count[KSUB];
__device__ int   g_idx[KSUB][NPTS];
__device__ float g_wn[KSUB][NPTS];

__global__ void zero_kernel(float* __restrict__ out) {
    int i = blockIdx.x * blockDim.x + threadIdx.x;
    if (i < NPTS) out[i] = 0.0f;
    if (i < KSUB) g_count[i] = 0;
}

__global__ void window_kernel(const float* __restrict__ x,
                              const float* __restrict__ xmins,
                              const float* __restrict__ xmaxs) {
    int n = blockIdx.x * blockDim.x + threadIdx.x;
    float x0 = x[2*n], x1 = x[2*n+1];
    float wr[KSUB];
    float s = 0.0f;
#pragma unroll
    for (int k = 0; k < KSUB; ++k) {
        float m0 = xmins[2*k],  m1 = xmins[2*k+1];
        float M0 = xmaxs[2*k],  M1 = xmaxs[2*k+1];
        float tl0 = fminf(fmaxf((x0 - (m0 - TWF)) * 2.5f, 0.f), 1.f);
        float tr0 = fminf(fmaxf(((M0 + TWF) - x0) * 2.5f, 0.f), 1.f);
        float tl1 = fminf(fmaxf((x1 - (m1 - TWF)) * 2.5f, 0.f), 1.f);
        float tr1 = fminf(fmaxf(((M1 + TWF) - x1) * 2.5f, 0.f), 1.f);
        float f0 = 0.25f * (1.f - cosf(PI_F*tl0)) * (1.f - cosf(PI_F*tr0));
        float f1 = 0.25f * (1.f - cosf(PI_F*tl1)) * (1.f - cosf(PI_F*tr1));
        wr[k] = f0 * f1;
        s += wr[k];
    }
    float inv = 1.0f / (s + 1e-9f);
    int lane = threadIdx.x & 31;
#pragma unroll
    for (int k = 0; k < KSUB; ++k) {
        float wn = wr[k] * inv;
        g_wn[k][n] = wn;
        bool act = (wr[k] > 0.0f);
        unsigned m = __ballot_sync(0xffffffffu, act);
        int cnt = __popc(m);
        int base = 0;
        if (lane == 0 && cnt) base = atomicAdd(&g_count[k], cnt);
        base = __shfl_sync(0xffffffffu, base, 0);
        if (act) {
            int off = __popc(m & ((1u << lane) - 1u));
            g_idx[k][base + off] = n;
        }
    }
}

__global__ void __launch_bounds__(256, 1)
mlp_kernel(const float* __restrict__ x,
           const float* __restrict__ W0, const float* __restrict__ b0,
           const float* __restrict__ W1, const float* __restrict__ b1,
           const float* __restrict__ W2, const float* __restrict__ b2,
           const float* __restrict__ W3, const float* __restrict__ b3,
           const float* __restrict__ xmins, const float* __restrict__ xmaxs,
           float* __restrict__ out) {
    extern __shared__ float sm[];
    float* bufA = sm;                       // 64*AS
    float* bufB = sm + 64*AS;               // 64*AS
    float* Ws   = sm + 2*64*AS;             // 32*256
    float* sxn  = Ws + 32*256;              // 64*2
    float* swn  = sxn + 128;                // 64
    int*   sidx = (int*)(swn + 64);         // 64

    int k   = blockIdx.y;
    int cnt = g_count[k];
    int p0  = blockIdx.x * 64;
    if (p0 >= cnt) return;
    int npts = min(64, cnt - p0);
    int tid  = threadIdx.x;

    if (tid < 64) {
        int i = g_idx[k][p0 + ((tid < npts) ? tid : 0)];
        sidx[tid] = i;
        float mn0 = xmins[2*k], mn1 = xmins[2*k+1];
        float mx0 = xmaxs[2*k], mx1 = xmaxs[2*k+1];
        float c0 = 0.5f*(mn0 + mx0), c1 = 0.5f*(mn1 + mx1);
        float s0 = fmaxf(0.5f*(mx0 - mn0), 1e-9f);
        float s1 = fmaxf(0.5f*(mx1 - mn1), 1e-9f);
        sxn[2*tid]   = (x[2*i]   - c0) / s0;
        sxn[2*tid+1] = (x[2*i+1] - c1) / s1;
        swn[tid] = g_wn[k][i];
    }
    __syncthreads();

    // ---- layer 0: [64,2] @ [2,256] + b, tanh -> bufA ----
    {
        const float* W0k = W0 + k*(2*WD);
        float w0a = W0k[tid], w0b = W0k[WD + tid], bb = b0[k*WD + tid];
#pragma unroll 4
        for (int p = 0; p < 64; ++p) {
            float v = sxn[2*p]*w0a + sxn[2*p+1]*w0b + bb;
            bufA[p*AS + tid] = tanhf(v);
        }
    }
    __syncthreads();

    // ---- layers 1 & 2: [64,256] @ [256,256] + b, tanh ----
    int cr = tid & 15, pr = tid >> 4;     // thread = (4 points) x (16 strided cols)
    const float* Wg_arr[2] = {W1 + k*WD*WD, W2 + k*WD*WD};
    const float* bg_arr[2] = {b1 + k*WD,    b2 + k*WD};
    float* A = bufA; float* C = bufB;
    for (int layer = 0; layer < 2; ++layer) {
        const float* Wg = Wg_arr[layer];
        const float* bg = bg_arr[layer];
        float acc[4][16];
#pragma unroll
        for (int j = 0; j < 16; ++j) {
            float bb = bg[cr + 16*j];
            acc[0][j] = bb; acc[1][j] = bb; acc[2][j] = bb; acc[3][j] = bb;
        }
        for (int kt = 0; kt < WD; kt += 32) {
            // stage 32x256 weight tile (rows = inner dim)
            const float4* src = (const float4*)(Wg + kt*WD);
            float4* dst = (float4*)Ws;
#pragma unroll
            for (int q = 0; q < 8; ++q)
                dst[tid + q*256] = src[tid + q*256];
            __syncthreads();
#pragma unroll
            for (int kk = 0; kk < 32; ++kk) {
                float a0 = A[(pr*4+0)*AS + kt+kk];
                float a1 = A[(pr*4+1)*AS + kt+kk];
                float a2 = A[(pr*4+2)*AS + kt+kk];
                float a3 = A[(pr*4+3)*AS + kt+kk];
#pragma unroll
                for (int j = 0; j < 16; ++j) {
                    float w = Ws[kk*WD + cr + 16*j];
                    acc[0][j] += a0*w;
                    acc[1][j] += a1*w;
                    acc[2][j] += a2*w;
                    acc[3][j] += a3*w;
                }
            }
            __syncthreads();
        }
#pragma unroll
        for (int i2 = 0; i2 < 4; ++i2)
#pragma unroll
            for (int j = 0; j < 16; ++j)
                C[(pr*4+i2)*AS + cr + 16*j] = tanhf(acc[i2][j]);
        __syncthreads();
        float* tswap = A; A = C; C = tswap;
    }

    // ---- layer 3: [64,256] @ [256,1] + b3, window-weighted atomic combine ----
    {
        const float* W3k = W3 + k*WD;
        int p = tid >> 2, s = tid & 3;
        float partial = 0.0f;
        int cbase = s * 64;
#pragma unroll 8
        for (int cc = 0; cc < 64; ++cc)
            partial += A[p*AS + cbase + cc] * W3k[cbase + cc];
        partial += __shfl_down_sync(0xffffffffu, partial, 2, 4);
        partial += __shfl_down_sync(0xffffffffu, partial, 1, 4);
        if (s == 0 && p < npts)
            atomicAdd(out + sidx[p], swn[p] * (partial + b3[k]));
    }
}

extern "C" void kernel_launch(void* const* d_in, const int* in_sizes, int n_in,
                              void* d_out, int out_size) {
    const float* x     = (const float*)d_in[0];
    const float* W0    = (const float*)d_in[1];
    const float* b0    = (const float*)d_in[2];
    const float* W1    = (const float*)d_in[3];
    const float* b1    = (const float*)d_in[4];
    const float* W2    = (const float*)d_in[5];
    const float* b2    = (const float*)d_in[6];
    const float* W3    = (const float*)d_in[7];
    const float* b3    = (const float*)d_in[8];
    const float* xmins = (const float*)d_in[9];
    const float* xmaxs = (const float*)d_in[10];
    float* out = (float*)d_out;

    cudaFuncSetAttribute(mlp_kernel,
                         cudaFuncAttributeMaxDynamicSharedMemorySize, SMEM_BYTES);

    zero_kernel<<<NPTS/256, 256>>>(out);
    window_kernel<<<NPTS/256, 256>>>(x, xmins, xmaxs);
    mlp_kernel<<<dim3(NPTS/64, KSUB), 256, SMEM_BYTES>>>(
        x, W0, b0, W1, b1, W2, b2, W3, b3, xmins, xmaxs, out);
}

// round 6
// speedup vs baseline: 3.0113x; 3.0113x over previous
#include <cuda_runtime.h>

#define NPTS 16384
#define KSUB 16
#define WD   256
#define TWF  0.2f
#define PI_F 3.14159265358979f
#define AS2  264              // padded row stride (floats) for A and W tiles
#define WCH  (32 * AS2)       // floats per W chunk buffer (32 k-rows)

// smem float offsets
#define F_A    0              // 128*264 = 33792 floats
#define F_W    33792          // 2 * WCH = 16896
#define F_XN   50688          // 256
#define F_WN   50944          // 128
#define F_IDX  51072          // 128
#define F_BIAS 51200          // 512 (b1,b2)
#define F_W3   51712          // 256
#define SMEM_FLOATS 51968
#define SMEM_BYTES  (SMEM_FLOATS * 4)

__device__ int   g_count[KSUB];
__device__ int   g_idx[KSUB][NPTS];
__device__ float g_wn[KSUB][NPTS];
__device__ float g_WT[2 * KSUB * WD * WD];   // tf32-pre-rounded W1,W2

__device__ __forceinline__ float rtf32(float x) {
    unsigned u; asm("cvt.rna.tf32.f32 %0, %1;" : "=r"(u) : "f"(x));
    return __uint_as_float(u);
}

// round W1,W2 to tf32 into g_WT; zero counters
__global__ void prep_kernel(const float* __restrict__ W1, const float* __restrict__ W2) {
    int i = blockIdx.x * 256 + threadIdx.x;
    float4* d = (float4*)g_WT;
#pragma unroll
    for (int q = 0; q < 4; ++q) {
        int f = i + q * 131072;                 // float4 index, total 524288
        const float4* s = (f < 262144) ? (const float4*)W1 : (const float4*)W2;
        int fs = (f < 262144) ? f : (f - 262144);
        float4 v = s[fs];
        v.x = rtf32(v.x); v.y = rtf32(v.y); v.z = rtf32(v.z); v.w = rtf32(v.w);
        d[f] = v;
    }
    if (blockIdx.x == 0 && threadIdx.x < KSUB) g_count[threadIdx.x] = 0;
}

__global__ void window_kernel(const float* __restrict__ x,
                              const float* __restrict__ xmins,
                              const float* __restrict__ xmaxs,
                              float* __restrict__ out) {
    int n = blockIdx.x * blockDim.x + threadIdx.x;
    out[n] = 0.0f;
    float x0 = x[2 * n], x1 = x[2 * n + 1];
    float wr[KSUB], s = 0.0f;
#pragma unroll
    for (int k = 0; k < KSUB; ++k) {
        float tl0 = fminf(fmaxf((x0 - (xmins[2 * k] - TWF)) * 2.5f, 0.f), 1.f);
        float tr0 = fminf(fmaxf(((xmaxs[2 * k] + TWF) - x0) * 2.5f, 0.f), 1.f);
        float tl1 = fminf(fmaxf((x1 - (xmins[2 * k + 1] - TWF)) * 2.5f, 0.f), 1.f);
        float tr1 = fminf(fmaxf(((xmaxs[2 * k + 1] + TWF) - x1) * 2.5f, 0.f), 1.f);
        float f0 = 0.25f * (1.f - cosf(PI_F * tl0)) * (1.f - cosf(PI_F * tr0));
        float f1 = 0.25f * (1.f - cosf(PI_F * tl1)) * (1.f - cosf(PI_F * tr1));
        wr[k] = f0 * f1; s += wr[k];
    }
    float inv = 1.0f / (s + 1e-9f);
    int lane = threadIdx.x & 31;
#pragma unroll
    for (int k = 0; k < KSUB; ++k) {
        g_wn[k][n] = wr[k] * inv;
        bool act = (wr[k] > 0.0f);
        unsigned m = __ballot_sync(0xffffffffu, act);
        int base = 0;
        if (lane == 0 && m) base = atomicAdd(&g_count[k], __popc(m));
        base = __shfl_sync(0xffffffffu, base, 0);
        if (act) g_idx[k][base + __popc(m & ((1u << lane) - 1u))] = n;
    }
}

__device__ __forceinline__ void stage_chunk(const float4* __restrict__ src,
                                            float* dstbase, int tid) {
#pragma unroll
    for (int q = 0; q < 8; ++q) {
        int f = q * 256 + tid;        // 2048 float4 per chunk
        int row = f >> 6, c4 = f & 63;
        unsigned dst = (unsigned)__cvta_generic_to_shared(dstbase + row * AS2 + c4 * 4);
        asm volatile("cp.async.cg.shared.global [%0], [%1], 16;"
                     :: "r"(dst), "l"(src + f) : "memory");
    }
    asm volatile("cp.async.commit_group;" ::: "memory");
}

__global__ void __launch_bounds__(256, 1)
mlp_kernel(const float* __restrict__ x,
           const float* __restrict__ W0, const float* __restrict__ b0,
           const float* __restrict__ b1, const float* __restrict__ b2,
           const float* __restrict__ W3, const float* __restrict__ b3,
           const float* __restrict__ xmins, const float* __restrict__ xmaxs,
           float* __restrict__ out) {
    extern __shared__ float smf[];
    int k = blockIdx.y, cnt = g_count[k], p0 = blockIdx.x * 128;
    if (p0 >= cnt) return;
    int npts = min(128, cnt - p0);
    int tid = threadIdx.x, wid = tid >> 5, lane = tid & 31;

    float* sxn = smf + F_XN;
    float* swn = smf + F_WN;
    int* sidx  = (int*)(smf + F_IDX);
    float* sbias = smf + F_BIAS;
    float* sw3 = smf + F_W3;

    // kick off weight chunk 0 (layer 1, chunk 0)
    stage_chunk((const float4*)(g_WT + k * 65536), smf + F_W, tid);

    if (tid < 128) {
        int i = g_idx[k][p0 + ((tid < npts) ? tid : (npts - 1))];
        sidx[tid] = i;
        float mn0 = xmins[2 * k], mn1 = xmins[2 * k + 1];
        float mx0 = xmaxs[2 * k], mx1 = xmaxs[2 * k + 1];
        float c0 = 0.5f * (mn0 + mx0), c1 = 0.5f * (mn1 + mx1);
        float s0 = fmaxf(0.5f * (mx0 - mn0), 1e-9f);
        float s1 = fmaxf(0.5f * (mx1 - mn1), 1e-9f);
        sxn[2 * tid] = (x[2 * i] - c0) / s0;
        sxn[2 * tid + 1] = (x[2 * i + 1] - c1) / s1;
        swn[tid] = g_wn[k][i];
    }
    sbias[tid] = b1[k * WD + tid];
    sbias[256 + tid] = b2[k * WD + tid];
    sw3[tid] = W3[k * WD + tid];
    float b3k = b3[k];
    __syncthreads();

    // layer 0: thread = output col v, 128 points
    {
        const float* W0k = W0 + k * 2 * WD;
        float wa = W0k[tid], wb = W0k[WD + tid], bb = b0[k * WD + tid];
#pragma unroll 4
        for (int p = 0; p < 128; ++p) {
            float v = fmaf(sxn[2 * p], wa, fmaf(sxn[2 * p + 1], wb, bb));
            smf[F_A + p * AS2 + tid] = rtf32(tanhf(v));
        }
    }

    int g = lane >> 2, t = lane & 3, n0 = wid * 32;
    float acc[8][4][4];

#pragma unroll 1
    for (int cc = 0; cc < 16; ++cc) {
        int layer = cc >> 3, c = cc & 7;
        asm volatile("cp.async.wait_group 0;" ::: "memory");
        __syncthreads();
        if (cc < 15) {
            int nx = cc + 1;
            stage_chunk((const float4*)(g_WT + ((nx >> 3) * KSUB + k) * 65536 + (nx & 7) * 8192),
                        smf + F_W + (nx & 1) * WCH, tid);
        }
        if (c == 0) {
#pragma unroll
            for (int m = 0; m < 8; ++m)
#pragma unroll
                for (int nt = 0; nt < 4; ++nt)
#pragma unroll
                    for (int r = 0; r < 4; ++r) acc[m][nt][r] = 0.f;
        }
        const float* Wb = smf + F_W + (cc & 1) * WCH;
        const float* Ar = smf + F_A;
#pragma unroll
        for (int ks = 0; ks < 4; ++ks) {
            int kw = ks * 8;
            unsigned b0r[4], b1r[4];
#pragma unroll
            for (int nt = 0; nt < 4; ++nt) {
                b0r[nt] = __float_as_uint(Wb[(kw + t) * AS2 + n0 + nt * 8 + g]);
                b1r[nt] = __float_as_uint(Wb[(kw + t + 4) * AS2 + n0 + nt * 8 + g]);
            }
            int ka = c * 32 + kw;
#pragma unroll
            for (int m = 0; m < 8; ++m) {
                unsigned a0 = __float_as_uint(Ar[(m * 16 + g) * AS2 + ka + t]);
                unsigned a1 = __float_as_uint(Ar[(m * 16 + 8 + g) * AS2 + ka + t]);
                unsigned a2 = __float_as_uint(Ar[(m * 16 + g) * AS2 + ka + t + 4]);
                unsigned a3 = __float_as_uint(Ar[(m * 16 + 8 + g) * AS2 + ka + t + 4]);
#pragma unroll
                for (int nt = 0; nt < 4; ++nt) {
                    asm volatile(
                        "mma.sync.aligned.m16n8k8.row.col.f32.tf32.tf32.f32 "
                        "{%0,%1,%2,%3}, {%4,%5,%6,%7}, {%8,%9}, {%0,%1,%2,%3};"
                        : "+f"(acc[m][nt][0]), "+f"(acc[m][nt][1]),
                          "+f"(acc[m][nt][2]), "+f"(acc[m][nt][3])
                        : "r"(a0), "r"(a1), "r"(a2), "r"(a3),
                          "r"(b0r[nt]), "r"(b1r[nt]));
                }
            }
        }
        if (c == 7) {  // layer done: bias + tanh -> back into A (tf32-rounded)
            __syncthreads();
            const float* sb = sbias + layer * 256;
            float* Aw = smf + F_A;
#pragma unroll
            for (int m = 0; m < 8; ++m) {
#pragma unroll
                for (int nt = 0; nt < 4; ++nt) {
                    int cb = n0 + nt * 8 + 2 * t;
                    float2 v0, v1;
                    v0.x = rtf32(tanhf(acc[m][nt][0] + sb[cb]));
                    v0.y = rtf32(tanhf(acc[m][nt][1] + sb[cb + 1]));
                    v1.x = rtf32(tanhf(acc[m][nt][2] + sb[cb]));
                    v1.y = rtf32(tanhf(acc[m][nt][3] + sb[cb + 1]));
                    *(float2*)(Aw + (m * 16 + g) * AS2 + cb) = v0;
                    *(float2*)(Aw + (m * 16 + 8 + g) * AS2 + cb) = v1;
                }
            }
            __syncthreads();
        }
    }

    // final: W3 dot + window-weighted combine. thread = (point, col-half)
    {
        int p = tid >> 1, s2 = tid & 1;
        const float* Ar = smf + F_A + p * AS2 + s2 * 128;
        const float* w3 = sw3 + s2 * 128;
        float partial = 0.0f;
#pragma unroll 16
        for (int c2 = 0; c2 < 128; ++c2) partial = fmaf(Ar[c2], w3[c2], partial);
        partial += __shfl_down_sync(0xffffffffu, partial, 1, 2);
        if (s2 == 0 && p < npts)
            atomicAdd(out + sidx[p], swn[p] * (partial + b3k));
    }
}

extern "C" void kernel_launch(void* const* d_in, const int* in_sizes, int n_in,
                              void* d_out, int out_size) {
    const float* x     = (const float*)d_in[0];
    const float* W0    = (const float*)d_in[1];
    const float* b0    = (const float*)d_in[2];
    const float* W1    = (const float*)d_in[3];
    const float* b1    = (const float*)d_in[4];
    const float* W2    = (const float*)d_in[5];
    const float* b2    = (const float*)d_in[6];
    const float* W3    = (const float*)d_in[7];
    const float* b3    = (const float*)d_in[8];
    const float* xmins = (const float*)d_in[9];
    const float* xmaxs = (const float*)d_in[10];
    float* out = (float*)d_out;

    cudaFuncSetAttribute(mlp_kernel,
                         cudaFuncAttributeMaxDynamicSharedMemorySize, SMEM_BYTES);

    prep_kernel<<<512, 256>>>(W1, W2);
    window_kernel<<<NPTS / 256, 256>>>(x, xmins, xmaxs, out);
    mlp_kernel<<<dim3(128, KSUB), 256, SMEM_BYTES>>>(
        x, W0, b0, b1, b2, W3, b3, xmins, xmaxs, out);
}

// round 9
// speedup vs baseline: 3.1877x; 1.0586x over previous
#include <cuda_runtime.h>

#define NPTS 16384
#define KSUB 16
#define WD   256
#define TWF  0.2f
#define PI_F 3.14159265358979f
#define AS2  264              // padded row stride (floats) for A and W tiles
#define WCH  (32 * AS2)       // floats per W chunk buffer (32 k-rows)

// smem float offsets
#define F_A    0              // 128*264 = 33792 floats
#define F_W    33792          // 2 * WCH = 16896
#define F_XN   50688          // 256
#define F_WN   50944          // 128
#define F_IDX  51072          // 128
#define F_BIAS 51200          // 512 (b1,b2)
#define F_W3   51712          // 256
#define SMEM_FLOATS 51968
#define SMEM_BYTES  (SMEM_FLOATS * 4)

__device__ int   g_count[KSUB];
__device__ int   g_idx[KSUB][NPTS];
__device__ float g_wn[KSUB][NPTS];
__device__ float g_WT[2 * KSUB * WD * WD];   // tf32-pre-rounded W1,W2

__device__ __forceinline__ float rtf32(float x) {
    unsigned u; asm("cvt.rna.tf32.f32 %0, %1;" : "=r"(u) : "f"(x));
    return __uint_as_float(u);
}
// fast tanh: 2/(1+e^-2x)-1. Saturates correctly; abs err ~1e-7 (MUFU ex2).
__device__ __forceinline__ float ftanh(float x) {
    float e = __expf(-2.0f * x);
    return __fdividef(2.0f, 1.0f + e) - 1.0f;
}

// round W1,W2 to tf32 into g_WT; zero counters
__global__ void prep_kernel(const float* __restrict__ W1, const float* __restrict__ W2) {
    int i = blockIdx.x * 256 + threadIdx.x;
    float4* d = (float4*)g_WT;
#pragma unroll
    for (int q = 0; q < 4; ++q) {
        int f = i + q * 131072;
        const float4* s = (f < 262144) ? (const float4*)W1 : (const float4*)W2;
        int fs = (f < 262144) ? f : (f - 262144);
        float4 v = s[fs];
        v.x = rtf32(v.x); v.y = rtf32(v.y); v.z = rtf32(v.z); v.w = rtf32(v.w);
        d[f] = v;
    }
    if (blockIdx.x == 0 && threadIdx.x < KSUB) g_count[threadIdx.x] = 0;
}

__global__ void window_kernel(const float* __restrict__ x,
                              const float* __restrict__ xmins,
                              const float* __restrict__ xmaxs,
                              float* __restrict__ out) {
    int n = blockIdx.x * blockDim.x + threadIdx.x;
    out[n] = 0.0f;
    float x0 = x[2 * n], x1 = x[2 * n + 1];
    float wr[KSUB], s = 0.0f;
#pragma unroll
    for (int k = 0; k < KSUB; ++k) {
        float tl0 = fminf(fmaxf((x0 - (xmins[2 * k] - TWF)) * 2.5f, 0.f), 1.f);
        float tr0 = fminf(fmaxf(((xmaxs[2 * k] + TWF) - x0) * 2.5f, 0.f), 1.f);
        float tl1 = fminf(fmaxf((x1 - (xmins[2 * k + 1] - TWF)) * 2.5f, 0.f), 1.f);
        float tr1 = fminf(fmaxf(((xmaxs[2 * k + 1] + TWF) - x1) * 2.5f, 0.f), 1.f);
        float f0 = 0.25f * (1.f - cosf(PI_F * tl0)) * (1.f - cosf(PI_F * tr0));
        float f1 = 0.25f * (1.f - cosf(PI_F * tl1)) * (1.f - cosf(PI_F * tr1));
        wr[k] = f0 * f1; s += wr[k];
    }
    float inv = 1.0f / (s + 1e-9f);
    int lane = threadIdx.x & 31;
#pragma unroll
    for (int k = 0; k < KSUB; ++k) {
        g_wn[k][n] = wr[k] * inv;
        bool act = (wr[k] > 0.0f);
        unsigned m = __ballot_sync(0xffffffffu, act);
        int base = 0;
        if (lane == 0 && m) base = atomicAdd(&g_count[k], __popc(m));
        base = __shfl_sync(0xffffffffu, base, 0);
        if (act) g_idx[k][base + __popc(m & ((1u << lane) - 1u))] = n;
    }
}

__device__ __forceinline__ void stage_chunk(const float4* __restrict__ src,
                                            float* dstbase, int tid) {
#pragma unroll
    for (int q = 0; q < 8; ++q) {
        int f = q * 256 + tid;        // 2048 float4 per chunk
        int row = f >> 6, c4 = f & 63;
        unsigned dst = (unsigned)__cvta_generic_to_shared(dstbase + row * AS2 + c4 * 4);
        asm volatile("cp.async.cg.shared.global [%0], [%1], 16;"
                     :: "r"(dst), "l"(src + f) : "memory");
    }
    asm volatile("cp.async.commit_group;" ::: "memory");
}

__global__ void __launch_bounds__(256, 1)
mlp_kernel(const float* __restrict__ x,
           const float* __restrict__ W0, const float* __restrict__ b0,
           const float* __restrict__ b1, const float* __restrict__ b2,
           const float* __restrict__ W3, const float* __restrict__ b3,
           const float* __restrict__ xmins, const float* __restrict__ xmaxs,
           float* __restrict__ out) {
    extern __shared__ float smf[];
    int k = blockIdx.y, cnt = g_count[k], p0 = blockIdx.x * 128;
    if (p0 >= cnt) return;
    int npts = min(128, cnt - p0);
    int tid = threadIdx.x, wid = tid >> 5, lane = tid & 31;

    float* sxn = smf + F_XN;
    float* swn = smf + F_WN;
    int* sidx  = (int*)(smf + F_IDX);
    float* sbias = smf + F_BIAS;
    float* sw3 = smf + F_W3;

    stage_chunk((const float4*)(g_WT + k * 65536), smf + F_W, tid);

    if (tid < 128) {
        int i = g_idx[k][p0 + ((tid < npts) ? tid : (npts - 1))];
        sidx[tid] = i;
        float mn0 = xmins[2 * k], mn1 = xmins[2 * k + 1];
        float mx0 = xmaxs[2 * k], mx1 = xmaxs[2 * k + 1];
        float c0 = 0.5f * (mn0 + mx0), c1 = 0.5f * (mn1 + mx1);
        float s0 = fmaxf(0.5f * (mx0 - mn0), 1e-9f);
        float s1 = fmaxf(0.5f * (mx1 - mn1), 1e-9f);
        sxn[2 * tid] = (x[2 * i] - c0) / s0;
        sxn[2 * tid + 1] = (x[2 * i + 1] - c1) / s1;
        swn[tid] = g_wn[k][i];
    }
    sbias[tid] = b1[k * WD + tid];
    sbias[256 + tid] = b2[k * WD + tid];
    sw3[tid] = W3[k * WD + tid];
    float b3k = b3[k];
    __syncthreads();

    // layer 0: thread = output col v, 128 points
    {
        const float* W0k = W0 + k * 2 * WD;
        float wa = W0k[tid], wb = W0k[WD + tid], bb = b0[k * WD + tid];
#pragma unroll 4
        for (int p = 0; p < 128; ++p) {
            float v = fmaf(sxn[2 * p], wa, fmaf(sxn[2 * p + 1], wb, bb));
            smf[F_A + p * AS2 + tid] = rtf32(ftanh(v));
        }
    }

    // warp grid: wn = wid&3 (4 n-groups of 64 cols), wm = wid>>2 (2 m-halves of 64 pts)
    int g = lane >> 2, t = lane & 3;
    int N0 = (wid & 3) * 64, M0 = (wid >> 2) * 64;
    float acc[4][8][4];

#pragma unroll 1
    for (int cc = 0; cc < 16; ++cc) {
        int layer = cc >> 3, c = cc & 7;
        asm volatile("cp.async.wait_group 0;" ::: "memory");
        __syncthreads();
        if (cc < 15) {
            int nx = cc + 1;
            stage_chunk((const float4*)(g_WT + ((nx >> 3) * KSUB + k) * 65536 + (nx & 7) * 8192),
                        smf + F_W + (nx & 1) * WCH, tid);
        }
        if (c == 0) {
#pragma unroll
            for (int m = 0; m < 4; ++m)
#pragma unroll
                for (int nt = 0; nt < 8; ++nt)
#pragma unroll
                    for (int r = 0; r < 4; ++r) acc[m][nt][r] = 0.f;
        }
        const float* Wb = smf + F_W + (cc & 1) * WCH;
        const float* Ar = smf + F_A;
#pragma unroll
        for (int ks = 0; ks < 4; ++ks) {
            int kw = ks * 8;
            unsigned b0r[8], b1r[8];
#pragma unroll
            for (int nt = 0; nt < 8; ++nt) {
                b0r[nt] = __float_as_uint(Wb[(kw + t) * AS2 + N0 + nt * 8 + g]);
                b1r[nt] = __float_as_uint(Wb[(kw + t + 4) * AS2 + N0 + nt * 8 + g]);
            }
            int ka = c * 32 + kw;
#pragma unroll
            for (int m = 0; m < 4; ++m) {
                int r0 = M0 + m * 16;
                unsigned a0 = __float_as_uint(Ar[(r0 + g) * AS2 + ka + t]);
                unsigned a1 = __float_as_uint(Ar[(r0 + 8 + g) * AS2 + ka + t]);
                unsigned a2 = __float_as_uint(Ar[(r0 + g) * AS2 + ka + t + 4]);
                unsigned a3 = __float_as_uint(Ar[(r0 + 8 + g) * AS2 + ka + t + 4]);
#pragma unroll
                for (int nt = 0; nt < 8; ++nt) {
                    asm volatile(
                        "mma.sync.aligned.m16n8k8.row.col.f32.tf32.tf32.f32 "
                        "{%0,%1,%2,%3}, {%4,%5,%6,%7}, {%8,%9}, {%0,%1,%2,%3};"
                        : "+f"(acc[m][nt][0]), "+f"(acc[m][nt][1]),
                          "+f"(acc[m][nt][2]), "+f"(acc[m][nt][3])
                        : "r"(a0), "r"(a1), "r"(a2), "r"(a3),
                          "r"(b0r[nt]), "r"(b1r[nt]));
                }
            }
        }
        if (c == 7) {  // layer done: bias + tanh -> back into A (tf32-rounded)
            __syncthreads();
            const float* sb = sbias + layer * 256;
            float* Aw = smf + F_A;
#pragma unroll
            for (int m = 0; m < 4; ++m) {
                int r0 = M0 + m * 16;
#pragma unroll
                for (int nt = 0; nt < 8; ++nt) {
                    int cb = N0 + nt * 8 + 2 * t;
                    float2 v0, v1;
                    v0.x = rtf32(ftanh(acc[m][nt][0] + sb[cb]));
                    v0.y = rtf32(ftanh(acc[m][nt][1] + sb[cb + 1]));
                    v1.x = rtf32(ftanh(acc[m][nt][2] + sb[cb]));
                    v1.y = rtf32(ftanh(acc[m][nt][3] + sb[cb + 1]));
                    *(float2*)(Aw + (r0 + g) * AS2 + cb) = v0;
                    *(float2*)(Aw + (r0 + 8 + g) * AS2 + cb) = v1;
                }
            }
            __syncthreads();
        }
    }

    // final: W3 dot + window-weighted combine. thread = (point, col-half)
    {
        int p = tid >> 1, s2 = tid & 1;
        const float* Ar = smf + F_A + p * AS2 + s2 * 128;
        const float* w3 = sw3 + s2 * 128;
        float partial = 0.0f;
#pragma unroll 16
        for (int c2 = 0; c2 < 128; ++c2) partial = fmaf(Ar[c2], w3[c2], partial);
        partial += __shfl_down_sync(0xffffffffu, partial, 1, 2);
        if (s2 == 0 && p < npts)
            atomicAdd(out + sidx[p], swn[p] * (partial + b3k));
    }
}

extern "C" void kernel_launch(void* const* d_in, const int* in_sizes, int n_in,
                              void* d_out, int out_size) {
    const float* x     = (const float*)d_in[0];
    const float* W0    = (const float*)d_in[1];
    const float* b0    = (const float*)d_in[2];
    const float* W1    = (const float*)d_in[3];
    const float* b1    = (const float*)d_in[4];
    const float* W2    = (const float*)d_in[5];
    const float* b2    = (const float*)d_in[6];
    const float* W3    = (const float*)d_in[7];
    const float* b3    = (const float*)d_in[8];
    const float* xmins = (const float*)d_in[9];
    const float* xmaxs = (const float*)d_in[10];
    float* out = (float*)d_out;

    cudaFuncSetAttribute(mlp_kernel,
                         cudaFuncAttributeMaxDynamicSharedMemorySize, SMEM_BYTES);

    prep_kernel<<<512, 256>>>(W1, W2);
    window_kernel<<<NPTS / 256, 256>>>(x, xmins, xmaxs, out);
    mlp_kernel<<<dim3(128, KSUB), 256, SMEM_BYTES>>>(
        x, W0, b0, b1, b2, W3, b3, xmins, xmaxs, out);
}

// round 11
// speedup vs baseline: 4.5275x; 1.4203x over previous
#include <cuda_runtime.h>
#include <cuda_fp16.h>

#define NPTS 16384
#define KSUB 16
#define WD   256
#define TWF  0.2f
#define PI_F 3.14159265358979f

#define A_STRIDE 264            // halves per A row (132 words, conflict-free frags)
#define W_STRIDE 40             // halves per W chunk row (80B, 16B-aligned, conflict-free)

// smem byte offsets
#define B_A    0                // 128*264 half = 67584
#define B_W    67584            // 2 * 256*40 half = 40960
#define B_XN   108544           // 256 f32
#define B_WN   109568           // 128 f32
#define B_IDX  110080           // 128 i32
#define B_BIAS 110592           // 512 f32
#define B_W3   112640           // 256 f32
#define SMEM_BYTES 113664

__device__ int    g_count[KSUB];
__device__ int    g_idx[KSUB][NPTS];
__device__ float  g_wn[KSUB][NPTS];
// fp16 n-major weights: [2][16][chunk 8][n 256][k 32]
__device__ __half g_WTh[2 * KSUB * WD * WD];

__device__ __forceinline__ float ftanh(float x) {
    float e = __expf(-2.0f * x);
    return __fdividef(2.0f, 1.0f + e) - 1.0f;
}

// transpose W1,W2 to n-major fp16; zero counters. 32 blocks, 256 thr.
__global__ void prep_kernel(const float* __restrict__ W1, const float* __restrict__ W2) {
    __shared__ __half tile[256][40];
    int l = blockIdx.x >> 4, ks = blockIdx.x & 15;
    const float* src = (l ? W2 : W1) + ks * WD * WD;
    __half* dst = g_WTh + (size_t)blockIdx.x * (WD * WD);
    int tid = threadIdx.x;
#pragma unroll 1
    for (int ch = 0; ch < 8; ++ch) {
        int w0 = ch * 32;
#pragma unroll
        for (int i = 0; i < 32; ++i)                 // thread tid = col v
            tile[tid][i] = __float2half_rn(src[(w0 + i) * WD + tid]);
        __syncthreads();
        uint4* gout = (uint4*)(dst + ch * 8192);
#pragma unroll
        for (int q = 0; q < 4; ++q) {
            int f = q * 256 + tid;                   // 1024 uint4 per chunk
            int v = f >> 2, qq = f & 3;
            gout[f] = *(uint4*)&tile[v][qq * 8];
        }
        __syncthreads();
    }
    if (blockIdx.x == 0 && tid < KSUB) g_count[tid] = 0;
}

__global__ void window_kernel(const float* __restrict__ x,
                              const float* __restrict__ xmins,
                              const float* __restrict__ xmaxs,
                              float* __restrict__ out) {
    int n = blockIdx.x * blockDim.x + threadIdx.x;
    out[n] = 0.0f;
    float x0 = x[2 * n], x1 = x[2 * n + 1];
    float wr[KSUB], s = 0.0f;
#pragma unroll
    for (int k = 0; k < KSUB; ++k) {
        float tl0 = fminf(fmaxf((x0 - (xmins[2 * k] - TWF)) * 2.5f, 0.f), 1.f);
        float tr0 = fminf(fmaxf(((xmaxs[2 * k] + TWF) - x0) * 2.5f, 0.f), 1.f);
        float tl1 = fminf(fmaxf((x1 - (xmins[2 * k + 1] - TWF)) * 2.5f, 0.f), 1.f);
        float tr1 = fminf(fmaxf(((xmaxs[2 * k + 1] + TWF) - x1) * 2.5f, 0.f), 1.f);
        float f0 = 0.25f * (1.f - cosf(PI_F * tl0)) * (1.f - cosf(PI_F * tr0));
        float f1 = 0.25f * (1.f - cosf(PI_F * tl1)) * (1.f - cosf(PI_F * tr1));
        wr[k] = f0 * f1; s += wr[k];
    }
    float inv = 1.0f / (s + 1e-9f);
    int lane = threadIdx.x & 31;
#pragma unroll
    for (int k = 0; k < KSUB; ++k) {
        g_wn[k][n] = wr[k] * inv;
        bool act = (wr[k] > 0.0f);
        unsigned m = __ballot_sync(0xffffffffu, act);
        int base = 0;
        if (lane == 0 && m) base = atomicAdd(&g_count[k], __popc(m));
        base = __shfl_sync(0xffffffffu, base, 0);
        if (act) g_idx[k][base + __popc(m & ((1u << lane) - 1u))] = n;
    }
}

// stage one fp16 chunk [256 n x 32 k] = 16KB into padded smem rows
__device__ __forceinline__ void stage_chunk16(const uint4* __restrict__ src,
                                              __half* dstbase, int tid) {
#pragma unroll
    for (int q = 0; q < 4; ++q) {
        int f = q * 256 + tid;                      // 1024 x 16B
        int n = f >> 2, qq = f & 3;
        unsigned dst = (unsigned)__cvta_generic_to_shared(dstbase + n * W_STRIDE + qq * 8);
        asm volatile("cp.async.cg.shared.global [%0], [%1], 16;"
                     :: "r"(dst), "l"(src + f) : "memory");
    }
    asm volatile("cp.async.commit_group;" ::: "memory");
}

__global__ void __launch_bounds__(256, 1)
mlp_kernel(const float* __restrict__ x,
           const float* __restrict__ W0, const float* __restrict__ b0,
           const float* __restrict__ b1, const float* __restrict__ b2,
           const float* __restrict__ W3, const float* __restrict__ b3,
           const float* __restrict__ xmins, const float* __restrict__ xmaxs,
           float* __restrict__ out) {
    extern __shared__ char smc[];
    int k = blockIdx.y, cnt = g_count[k], p0 = blockIdx.x * 128;
    if (p0 >= cnt) return;
    int npts = min(128, cnt - p0);
    int tid = threadIdx.x, wid = tid >> 5, lane = tid & 31;

    __half* A  = (__half*)(smc + B_A);
    __half* Wb0 = (__half*)(smc + B_W);
    float* sxn = (float*)(smc + B_XN);
    float* swn = (float*)(smc + B_WN);
    int* sidx  = (int*)(smc + B_IDX);
    float* sbias = (float*)(smc + B_BIAS);
    float* sw3 = (float*)(smc + B_W3);

    stage_chunk16((const uint4*)(g_WTh + (size_t)k * WD * WD), Wb0, tid);

    if (tid < 128) {
        int i = g_idx[k][p0 + ((tid < npts) ? tid : (npts - 1))];
        sidx[tid] = i;
        float mn0 = xmins[2 * k], mn1 = xmins[2 * k + 1];
        float mx0 = xmaxs[2 * k], mx1 = xmaxs[2 * k + 1];
        float c0 = 0.5f * (mn0 + mx0), c1 = 0.5f * (mn1 + mx1);
        float s0 = fmaxf(0.5f * (mx0 - mn0), 1e-9f);
        float s1 = fmaxf(0.5f * (mx1 - mn1), 1e-9f);
        sxn[2 * tid] = (x[2 * i] - c0) / s0;
        sxn[2 * tid + 1] = (x[2 * i + 1] - c1) / s1;
        swn[tid] = g_wn[k][i];
    }
    sbias[tid] = b1[k * WD + tid];
    sbias[256 + tid] = b2[k * WD + tid];
    sw3[tid] = W3[k * WD + tid];
    float b3k = b3[k];
    __syncthreads();

    // layer 0: thread = (point-half ph, col-pair c2); writes half2, conflict-free
    {
        const float* W0k = W0 + k * 2 * WD;
        int c2 = tid & 127, ph = tid >> 7;
        int v0 = 2 * c2;
        float wa0 = W0k[v0], wb0v = W0k[WD + v0];
        float wa1 = W0k[v0 + 1], wb1v = W0k[WD + v0 + 1];
        float ba = b0[k * WD + v0], bb = b0[k * WD + v0 + 1];
        __half2* Arow = (__half2*)(A) + c2;          // col pair c2
#pragma unroll 4
        for (int pp = 0; pp < 64; ++pp) {
            int p = ph * 64 + pp;
            float xa = sxn[2 * p], xb = sxn[2 * p + 1];
            float u0 = ftanh(fmaf(xa, wa0, fmaf(xb, wb0v, ba)));
            float u1 = ftanh(fmaf(xa, wa1, fmaf(xb, wb1v, bb)));
            Arow[p * (A_STRIDE / 2)] = __floats2half2_rn(u0, u1);
        }
    }

    // warp grid: 4 n-groups of 64 cols, 2 m-halves of 64 points
    int g = lane >> 2, t = lane & 3;
    int N0 = (wid & 3) * 64, M0 = (wid >> 2) * 64;
    float acc[4][8][4];

#pragma unroll 1
    for (int cc = 0; cc < 16; ++cc) {
        int layer = cc >> 3, c = cc & 7;
        asm volatile("cp.async.wait_group 0;" ::: "memory");
        __syncthreads();
        if (cc < 15) {
            int nx = cc + 1;
            stage_chunk16((const uint4*)(g_WTh +
                          (size_t)(((nx >> 3) * KSUB + k) * 8 + (nx & 7)) * 8192),
                          Wb0 + (nx & 1) * (256 * W_STRIDE), tid);
        }
        if (c == 0) {
#pragma unroll
            for (int m = 0; m < 4; ++m)
#pragma unroll
                for (int nt = 0; nt < 8; ++nt)
#pragma unroll
                    for (int r = 0; r < 4; ++r) acc[m][nt][r] = 0.f;
        }
        const __half* Wc = Wb0 + (cc & 1) * (256 * W_STRIDE);
#pragma unroll
        for (int ks = 0; ks < 2; ++ks) {            // two k16 steps per 32-k chunk
            unsigned br0[8], br1[8];
#pragma unroll
            for (int nt = 0; nt < 8; ++nt) {
                const __half* wp = Wc + (N0 + nt * 8 + g) * W_STRIDE + ks * 16 + 2 * t;
                br0[nt] = *(const unsigned*)wp;          // k = 2t, 2t+1
                br1[nt] = *(const unsigned*)(wp + 8);    // k = 2t+8, 2t+9
            }
            int ka = c * 32 + ks * 16 + 2 * t;
#pragma unroll
            for (int m = 0; m < 4; ++m) {
                int r0 = M0 + m * 16;
                const __half* ap = A + (r0 + g) * A_STRIDE + ka;
                unsigned a0 = *(const unsigned*)ap;
                unsigned a1 = *(const unsigned*)(ap + 8 * A_STRIDE);
                unsigned a2 = *(const unsigned*)(ap + 8);
                unsigned a3 = *(const unsigned*)(ap + 8 * A_STRIDE + 8);
#pragma unroll
                for (int nt = 0; nt < 8; ++nt) {
                    asm volatile(
                        "mma.sync.aligned.m16n8k16.row.col.f32.f16.f16.f32 "
                        "{%0,%1,%2,%3}, {%4,%5,%6,%7}, {%8,%9}, {%0,%1,%2,%3};"
                        : "+f"(acc[m][nt][0]), "+f"(acc[m][nt][1]),
                          "+f"(acc[m][nt][2]), "+f"(acc[m][nt][3])
                        : "r"(a0), "r"(a1), "r"(a2), "r"(a3),
                          "r"(br0[nt]), "r"(br1[nt]));
                }
            }
        }
        if (c == 7) {   // layer done: bias + tanh -> back into A as fp16
            __syncthreads();
            const float* sb = sbias + layer * 256;
#pragma unroll
            for (int m = 0; m < 4; ++m) {
                int r0 = M0 + m * 16;
#pragma unroll
                for (int nt = 0; nt < 8; ++nt) {
                    int cb = N0 + nt * 8 + 2 * t;
                    float bx = sb[cb], by = sb[cb + 1];
                    __half2 v0 = __floats2half2_rn(ftanh(acc[m][nt][0] + bx),
                                                   ftanh(acc[m][nt][1] + by));
                    __half2 v1 = __floats2half2_rn(ftanh(acc[m][nt][2] + bx),
                                                   ftanh(acc[m][nt][3] + by));
                    *(__half2*)(A + (r0 + g) * A_STRIDE + cb) = v0;
                    *(__half2*)(A + (r0 + 8 + g) * A_STRIDE + cb) = v1;
                }
            }
            __syncthreads();
        }
    }

    // final: W3 dot + window-weighted combine. thread = (point, col-half)
    {
        int p = tid >> 1, s2 = tid & 1;
        const __half2* Ar = (const __half2*)(A + p * A_STRIDE + s2 * 128);
        const float* w3 = sw3 + s2 * 128;
        float partial = 0.0f;
#pragma unroll 16
        for (int c2 = 0; c2 < 64; ++c2) {
            float2 v = __half22float2(Ar[c2]);
            partial = fmaf(v.x, w3[2 * c2], fmaf(v.y, w3[2 * c2 + 1], partial));
        }
        partial += __shfl_down_sync(0xffffffffu, partial, 1, 2);
        if (s2 == 0 && p < npts)
            atomicAdd(out + sidx[p], swn[p] * (partial + b3k));
    }
}

extern "C" void kernel_launch(void* const* d_in, const int* in_sizes, int n_in,
                              void* d_out, int out_size) {
    const float* x     = (const float*)d_in[0];
    const float* W0    = (const float*)d_in[1];
    const float* b0    = (const float*)d_in[2];
    const float* W1    = (const float*)d_in[3];
    const float* b1    = (const float*)d_in[4];
    const float* W2    = (const float*)d_in[5];
    const float* b2    = (const float*)d_in[6];
    const float* W3    = (const float*)d_in[7];
    const float* b3    = (const float*)d_in[8];
    const float* xmins = (const float*)d_in[9];
    const float* xmaxs = (const float*)d_in[10];
    float* out = (float*)d_out;

    cudaFuncSetAttribute(mlp_kernel,
                         cudaFuncAttributeMaxDynamicSharedMemorySize, SMEM_BYTES);

    prep_kernel<<<32, 256>>>(W1, W2);
    window_kernel<<<NPTS / 256, 256>>>(x, xmins, xmaxs, out);
    mlp_kernel<<<dim3(128, KSUB), 256, SMEM_BYTES>>>(
        x, W0, b0, b1, b2, W3, b3, xmins, xmaxs, out);
}

// round 12
// speedup vs baseline: 4.8434x; 1.0698x over previous
#include <cuda_runtime.h>
#include <cuda_fp16.h>

#define NPTS 16384
#define KSUB 16
#define WD   256
#define TWF  0.2f
#define PI_F 3.14159265358979f

#define A_STRIDE 264            // halves per A row
#define W_STRIDE 40             // halves per W chunk row

// smem byte offsets
#define B_A    0                // 128*264 half = 67584
#define B_W    67584            // 2 * 256*40 half = 40960
#define B_XN   108544           // 256 f32
#define B_WN   109568           // 128 f32
#define B_IDX  110080           // 128 i32
#define B_BIAS 110592           // 512 f32
#define B_W3   112640           // 256 f32
#define SMEM_BYTES 113664

#define NTHR 512

__device__ int    g_count[KSUB];
__device__ int    g_idx[KSUB][NPTS];
__device__ float  g_wn[KSUB][NPTS];
// fp16 n-major weights: [2][16][chunk 8][n 256][k 32]
__device__ __half g_WTh[2 * KSUB * WD * WD];

__device__ __forceinline__ float ftanh(float x) {
    float e = __expf(-2.0f * x);
    return __fdividef(2.0f, 1.0f + e) - 1.0f;
}

// transpose one 32k x 256n chunk per block -> n-major fp16. 256 blocks x 256 thr.
__global__ void prep_kernel(const float* __restrict__ W1, const float* __restrict__ W2) {
    __shared__ __half tile[256][40];
    int b = blockIdx.x;
    int l = b >> 7, ks = (b >> 3) & 15, ch = b & 7;
    const float* src = (l ? W2 : W1) + ks * WD * WD + ch * 32 * WD;
    __half* dst = g_WTh + (size_t)((l * KSUB + ks) * 8 + ch) * 8192;
    int tid = threadIdx.x;
#pragma unroll
    for (int i = 0; i < 32; ++i)                    // thread tid = col n (coalesced)
        tile[tid][i] = __float2half_rn(src[i * WD + tid]);
    __syncthreads();
    uint4* gout = (uint4*)dst;
#pragma unroll
    for (int q = 0; q < 4; ++q) {
        int f = q * 256 + tid;                      // 1024 uint4
        int v = f >> 2, qq = f & 3;
        gout[f] = *(uint4*)&tile[v][qq * 8];
    }
    if (b == 0 && tid < KSUB) g_count[tid] = 0;
}

__global__ void window_kernel(const float* __restrict__ x,
                              const float* __restrict__ xmins,
                              const float* __restrict__ xmaxs,
                              float* __restrict__ out) {
    int n = blockIdx.x * blockDim.x + threadIdx.x;
    out[n] = 0.0f;
    float x0 = x[2 * n], x1 = x[2 * n + 1];
    float wr[KSUB], s = 0.0f;
#pragma unroll
    for (int k = 0; k < KSUB; ++k) {
        float tl0 = fminf(fmaxf((x0 - (xmins[2 * k] - TWF)) * 2.5f, 0.f), 1.f);
        float tr0 = fminf(fmaxf(((xmaxs[2 * k] + TWF) - x0) * 2.5f, 0.f), 1.f);
        float tl1 = fminf(fmaxf((x1 - (xmins[2 * k + 1] - TWF)) * 2.5f, 0.f), 1.f);
        float tr1 = fminf(fmaxf(((xmaxs[2 * k + 1] + TWF) - x1) * 2.5f, 0.f), 1.f);
        float f0 = 0.25f * (1.f - cosf(PI_F * tl0)) * (1.f - cosf(PI_F * tr0));
        float f1 = 0.25f * (1.f - cosf(PI_F * tl1)) * (1.f - cosf(PI_F * tr1));
        wr[k] = f0 * f1; s += wr[k];
    }
    float inv = 1.0f / (s + 1e-9f);
    int lane = threadIdx.x & 31;
#pragma unroll
    for (int k = 0; k < KSUB; ++k) {
        g_wn[k][n] = wr[k] * inv;
        bool act = (wr[k] > 0.0f);
        unsigned m = __ballot_sync(0xffffffffu, act);
        int base = 0;
        if (lane == 0 && m) base = atomicAdd(&g_count[k], __popc(m));
        base = __shfl_sync(0xffffffffu, base, 0);
        if (act) g_idx[k][base + __popc(m & ((1u << lane) - 1u))] = n;
    }
}

// stage one fp16 chunk [256 n x 32 k] = 16KB (512 threads: 2 x 16B each)
__device__ __forceinline__ void stage_chunk16(const uint4* __restrict__ src,
                                              __half* dstbase, int tid) {
#pragma unroll
    for (int q = 0; q < 2; ++q) {
        int f = q * NTHR + tid;
        int n = f >> 2, qq = f & 3;
        unsigned dst = (unsigned)__cvta_generic_to_shared(dstbase + n * W_STRIDE + qq * 8);
        asm volatile("cp.async.cg.shared.global [%0], [%1], 16;"
                     :: "r"(dst), "l"(src + f) : "memory");
    }
    asm volatile("cp.async.commit_group;" ::: "memory");
}

__global__ void __launch_bounds__(NTHR, 1)
mlp_kernel(const float* __restrict__ x,
           const float* __restrict__ W0, const float* __restrict__ b0,
           const float* __restrict__ b1, const float* __restrict__ b2,
           const float* __restrict__ W3, const float* __restrict__ b3,
           const float* __restrict__ xmins, const float* __restrict__ xmaxs,
           float* __restrict__ out) {
    extern __shared__ char smc[];
    int k = blockIdx.y, cnt = g_count[k], p0 = blockIdx.x * 128;
    if (p0 >= cnt) return;
    int npts = min(128, cnt - p0);
    int tid = threadIdx.x, wid = tid >> 5, lane = tid & 31;

    __half* A  = (__half*)(smc + B_A);
    __half* Wb0 = (__half*)(smc + B_W);
    float* sxn = (float*)(smc + B_XN);
    float* swn = (float*)(smc + B_WN);
    int* sidx  = (int*)(smc + B_IDX);
    float* sbias = (float*)(smc + B_BIAS);
    float* sw3 = (float*)(smc + B_W3);

    stage_chunk16((const uint4*)(g_WTh + (size_t)k * WD * WD), Wb0, tid);

    if (tid < 128) {
        int i = g_idx[k][p0 + ((tid < npts) ? tid : (npts - 1))];
        sidx[tid] = i;
        float mn0 = xmins[2 * k], mn1 = xmins[2 * k + 1];
        float mx0 = xmaxs[2 * k], mx1 = xmaxs[2 * k + 1];
        float c0 = 0.5f * (mn0 + mx0), c1 = 0.5f * (mn1 + mx1);
        float s0 = fmaxf(0.5f * (mx0 - mn0), 1e-9f);
        float s1 = fmaxf(0.5f * (mx1 - mn1), 1e-9f);
        sxn[2 * tid] = (x[2 * i] - c0) / s0;
        sxn[2 * tid + 1] = (x[2 * i + 1] - c1) / s1;
        swn[tid] = g_wn[k][i];
    } else if (tid < 384) {
        int t2 = tid - 128;
        if (t2 < 256) { sbias[t2] = b1[k * WD + t2]; }
    }
    if (tid >= 384) {
        int t2 = tid - 384;
        sbias[256 + t2] = b2[k * WD + t2];
        sbias[384 + t2] = b2[k * WD + 128 + t2];    // t2<128
    }
    if (tid < 256) sw3[tid] = W3[k * WD + tid];
    float b3k = b3[k];
    __syncthreads();

    // layer 0: thread = (point-group pg of 32, col-pair c2)
    {
        const float* W0k = W0 + k * 2 * WD;
        int c2 = tid & 127, pg = tid >> 7;
        int v0 = 2 * c2;
        float wa0 = W0k[v0], wb0v = W0k[WD + v0];
        float wa1 = W0k[v0 + 1], wb1v = W0k[WD + v0 + 1];
        float ba = b0[k * WD + v0], bb = b0[k * WD + v0 + 1];
        __half2* Arow = (__half2*)(A) + c2;
#pragma unroll 4
        for (int pp = 0; pp < 32; ++pp) {
            int p = pg * 32 + pp;
            float xa = sxn[2 * p], xb = sxn[2 * p + 1];
            float u0 = ftanh(fmaf(xa, wa0, fmaf(xb, wb0v, ba)));
            float u1 = ftanh(fmaf(xa, wa1, fmaf(xb, wb1v, bb)));
            Arow[p * (A_STRIDE / 2)] = __floats2half2_rn(u0, u1);
        }
    }

    // warp grid: 4 n-groups of 64 cols x 4 m-groups of 32 points
    int g = lane >> 2, t = lane & 3;
    int N0 = (wid & 3) * 64, M0 = (wid >> 2) * 32;
    float acc[2][8][4];

#pragma unroll 1
    for (int cc = 0; cc < 16; ++cc) {
        int layer = cc >> 3, c = cc & 7;
        asm volatile("cp.async.wait_group 0;" ::: "memory");
        __syncthreads();
        if (cc < 15) {
            int nx = cc + 1;
            stage_chunk16((const uint4*)(g_WTh +
                          (size_t)(((nx >> 3) * KSUB + k) * 8 + (nx & 7)) * 8192),
                          Wb0 + (nx & 1) * (256 * W_STRIDE), tid);
        }
        if (c == 0) {
#pragma unroll
            for (int m = 0; m < 2; ++m)
#pragma unroll
                for (int nt = 0; nt < 8; ++nt)
#pragma unroll
                    for (int r = 0; r < 4; ++r) acc[m][nt][r] = 0.f;
        }
        const __half* Wc = Wb0 + (cc & 1) * (256 * W_STRIDE);
#pragma unroll
        for (int ks = 0; ks < 2; ++ks) {
            unsigned br0[8], br1[8];
#pragma unroll
            for (int nt = 0; nt < 8; ++nt) {
                const __half* wp = Wc + (N0 + nt * 8 + g) * W_STRIDE + ks * 16 + 2 * t;
                br0[nt] = *(const unsigned*)wp;
                br1[nt] = *(const unsigned*)(wp + 8);
            }
            int ka = c * 32 + ks * 16 + 2 * t;
#pragma unroll
            for (int m = 0; m < 2; ++m) {
                int r0 = M0 + m * 16;
                const __half* ap = A + (r0 + g) * A_STRIDE + ka;
                unsigned a0 = *(const unsigned*)ap;
                unsigned a1 = *(const unsigned*)(ap + 8 * A_STRIDE);
                unsigned a2 = *(const unsigned*)(ap + 8);
                unsigned a3 = *(const unsigned*)(ap + 8 * A_STRIDE + 8);
#pragma unroll
                for (int nt = 0; nt < 8; ++nt) {
                    asm volatile(
                        "mma.sync.aligned.m16n8k16.row.col.f32.f16.f16.f32 "
                        "{%0,%1,%2,%3}, {%4,%5,%6,%7}, {%8,%9}, {%0,%1,%2,%3};"
                        : "+f"(acc[m][nt][0]), "+f"(acc[m][nt][1]),
                          "+f"(acc[m][nt][2]), "+f"(acc[m][nt][3])
                        : "r"(a0), "r"(a1), "r"(a2), "r"(a3),
                          "r"(br0[nt]), "r"(br1[nt]));
                }
            }
        }
        if (c == 7) {   // layer done: bias + tanh -> back into A as fp16
            __syncthreads();
            const float* sb = sbias + layer * 256;
#pragma unroll
            for (int m = 0; m < 2; ++m) {
                int r0 = M0 + m * 16;
#pragma unroll
                for (int nt = 0; nt < 8; ++nt) {
                    int cb = N0 + nt * 8 + 2 * t;
                    float bx = sb[cb], by = sb[cb + 1];
                    __half2 v0 = __floats2half2_rn(ftanh(acc[m][nt][0] + bx),
                                                   ftanh(acc[m][nt][1] + by));
                    __half2 v1 = __floats2half2_rn(ftanh(acc[m][nt][2] + bx),
                                                   ftanh(acc[m][nt][3] + by));
                    *(__half2*)(A + (r0 + g) * A_STRIDE + cb) = v0;
                    *(__half2*)(A + (r0 + 8 + g) * A_STRIDE + cb) = v1;
                }
            }
            __syncthreads();
        }
    }

    // final: W3 dot + combine. thread = (point p, quarter s4 of 64 cols)
    {
        int p = tid >> 2, s4 = tid & 3;
        const __half2* Ar = (const __half2*)(A + p * A_STRIDE + s4 * 64);
        const float* w3 = sw3 + s4 * 64;
        float partial = 0.0f;
#pragma unroll 8
        for (int c2 = 0; c2 < 32; ++c2) {
            float2 v = __half22float2(Ar[c2]);
            partial = fmaf(v.x, w3[2 * c2], fmaf(v.y, w3[2 * c2 + 1], partial));
        }
        partial += __shfl_down_sync(0xffffffffu, partial, 2, 4);
        partial += __shfl_down_sync(0xffffffffu, partial, 1, 4);
        if (s4 == 0 && p < npts)
            atomicAdd(out + sidx[p], swn[p] * (partial + b3k));
    }
}

extern "C" void kernel_launch(void* const* d_in, const int* in_sizes, int n_in,
                              void* d_out, int out_size) {
    const float* x     = (const float*)d_in[0];
    const float* W0    = (const float*)d_in[1];
    const float* b0    = (const float*)d_in[2];
    const float* W1    = (const float*)d_in[3];
    const float* b1    = (const float*)d_in[4];
    const float* W2    = (const float*)d_in[5];
    const float* b2    = (const float*)d_in[6];
    const float* W3    = (const float*)d_in[7];
    const float* b3    = (const float*)d_in[8];
    const float* xmins = (const float*)d_in[9];
    const float* xmaxs = (const float*)d_in[10];
    float* out = (float*)d_out;

    cudaFuncSetAttribute(mlp_kernel,
                         cudaFuncAttributeMaxDynamicSharedMemorySize, SMEM_BYTES);

    prep_kernel<<<256, 256>>>(W1, W2);
    window_kernel<<<NPTS / 256, 256>>>(x, xmins, xmaxs, out);
    mlp_kernel<<<dim3(128, KSUB), NTHR, SMEM_BYTES>>>(
        x, W0, b0, b1, b2, W3, b3, xmins, xmaxs, out);
}

// round 14
// speedup vs baseline: 4.9070x; 1.0131x over previous
#include <cuda_runtime.h>
#include <cuda_fp16.h>

#define NPTS 16384
#define KSUB 16
#define WD   256
#define TWF  0.2f
#define PI_F 3.14159265358979f

#define A_STRIDE 264            // halves per A row (33x16B: ldmatrix conflict-free)
#define W_STRIDE 40             // halves per W row (5x16B: ldmatrix conflict-free)
#define WBUF_HALVES (256 * W_STRIDE)
#define WBUF_BYTES  (WBUF_HALVES * 2)

// smem byte offsets
#define B_A    0                // 128*264*2 = 67584
#define B_W    67584            // 4 * 20480 = 81920
#define B_XN   149504           // 256 f32
#define B_WN   150528           // 128 f32
#define B_IDX  151040           // 128 i32
#define B_BIAS 151552           // 512 f32
#define B_W3   153600           // 256 f32
#define SMEM_BYTES 154624

#define NTHR 512

__device__ int    g_count[KSUB];
__device__ int    g_idx[KSUB][NPTS];
__device__ float  g_wn[KSUB][NPTS];
// fp16 n-major weights: [2][16][chunk 8][n 256][k 32]
__device__ __half g_WTh[2 * KSUB * WD * WD];

__device__ __forceinline__ float ftanh(float x) {
    float e = __expf(-2.0f * x);
    return __fdividef(2.0f, 1.0f + e) - 1.0f;
}

// transpose one 32k x 256n chunk per block -> n-major fp16. 256 blocks x 256 thr.
__global__ void prep_kernel(const float* __restrict__ W1, const float* __restrict__ W2) {
    __shared__ __half tile[256][40];
    int b = blockIdx.x;
    int l = b >> 7, ks = (b >> 3) & 15, ch = b & 7;
    const float* src = (l ? W2 : W1) + ks * WD * WD + ch * 32 * WD;
    __half* dst = g_WTh + (size_t)((l * KSUB + ks) * 8 + ch) * 8192;
    int tid = threadIdx.x;
#pragma unroll
    for (int i = 0; i < 32; ++i)
        tile[tid][i] = __float2half_rn(src[i * WD + tid]);
    __syncthreads();
    uint4* gout = (uint4*)dst;
#pragma unroll
    for (int q = 0; q < 4; ++q) {
        int f = q * 256 + tid;
        int v = f >> 2, qq = f & 3;
        gout[f] = *(uint4*)&tile[v][qq * 8];
    }
    if (b == 0 && tid < KSUB) g_count[tid] = 0;
}

__global__ void window_kernel(const float* __restrict__ x,
                              const float* __restrict__ xmins,
                              const float* __restrict__ xmaxs,
                              float* __restrict__ out) {
    int n = blockIdx.x * blockDim.x + threadIdx.x;
    out[n] = 0.0f;
    float x0 = x[2 * n], x1 = x[2 * n + 1];
    float wr[KSUB], s = 0.0f;
#pragma unroll
    for (int k = 0; k < KSUB; ++k) {
        float tl0 = fminf(fmaxf((x0 - (xmins[2 * k] - TWF)) * 2.5f, 0.f), 1.f);
        float tr0 = fminf(fmaxf(((xmaxs[2 * k] + TWF) - x0) * 2.5f, 0.f), 1.f);
        float tl1 = fminf(fmaxf((x1 - (xmins[2 * k + 1] - TWF)) * 2.5f, 0.f), 1.f);
        float tr1 = fminf(fmaxf(((xmaxs[2 * k + 1] + TWF) - x1) * 2.5f, 0.f), 1.f);
        float f0 = 0.25f * (1.f - cosf(PI_F * tl0)) * (1.f - cosf(PI_F * tr0));
        float f1 = 0.25f * (1.f - cosf(PI_F * tl1)) * (1.f - cosf(PI_F * tr1));
        wr[k] = f0 * f1; s += wr[k];
    }
    float inv = 1.0f / (s + 1e-9f);
    int lane = threadIdx.x & 31;
#pragma unroll
    for (int k = 0; k < KSUB; ++k) {
        g_wn[k][n] = wr[k] * inv;
        bool act = (wr[k] > 0.0f);
        unsigned m = __ballot_sync(0xffffffffu, act);
        int base = 0;
        if (lane == 0 && m) base = atomicAdd(&g_count[k], __popc(m));
        base = __shfl_sync(0xffffffffu, base, 0);
        if (act) g_idx[k][base + __popc(m & ((1u << lane) - 1u))] = n;
    }
}

// stage one fp16 chunk [256 n x 32 k] = 16KB (512 threads: 2 x 16B each)
__device__ __forceinline__ void stage_chunk16(const uint4* __restrict__ src,
                                              __half* dstbase, int tid) {
#pragma unroll
    for (int q = 0; q < 2; ++q) {
        int f = q * NTHR + tid;
        int n = f >> 2, qq = f & 3;
        unsigned dst = (unsigned)__cvta_generic_to_shared(dstbase + n * W_STRIDE + qq * 8);
        asm volatile("cp.async.cg.shared.global [%0], [%1], 16;"
                     :: "r"(dst), "l"(src + f) : "memory");
    }
    asm volatile("cp.async.commit_group;" ::: "memory");
}

#define LDM_X4(r0, r1, r2, r3, addr) \
    asm volatile("ldmatrix.sync.aligned.m8n8.x4.shared.b16 {%0,%1,%2,%3}, [%4];" \
        : "=r"(r0), "=r"(r1), "=r"(r2), "=r"(r3) : "r"(addr))

__global__ void __launch_bounds__(NTHR, 1)
mlp_kernel(const float* __restrict__ x,
           const float* __restrict__ W0, const float* __restrict__ b0,
           const float* __restrict__ b1, const float* __restrict__ b2,
           const float* __restrict__ W3, const float* __restrict__ b3,
           const float* __restrict__ xmins, const float* __restrict__ xmaxs,
           float* __restrict__ out) {
    extern __shared__ char smc[];
    int k = blockIdx.y, cnt = g_count[k], p0 = blockIdx.x * 128;
    if (p0 >= cnt) return;
    int npts = min(128, cnt - p0);
    int tid = threadIdx.x, wid = tid >> 5, lane = tid & 31;

    __half* A  = (__half*)(smc + B_A);
    __half* Wb = (__half*)(smc + B_W);
    float* sxn = (float*)(smc + B_XN);
    float* swn = (float*)(smc + B_WN);
    int* sidx  = (int*)(smc + B_IDX);
    float* sbias = (float*)(smc + B_BIAS);
    float* sw3 = (float*)(smc + B_W3);

    const __half* wsrc = g_WTh + (size_t)k * WD * WD;   // layer1 base for this k
    // prologue: chunks 0,1,2 into buffers 0,1,2
    stage_chunk16((const uint4*)(wsrc), Wb, tid);
    stage_chunk16((const uint4*)(wsrc + 8192), Wb + WBUF_HALVES, tid);
    stage_chunk16((const uint4*)(wsrc + 16384), Wb + 2 * WBUF_HALVES, tid);

    if (tid < 128) {
        int i = g_idx[k][p0 + ((tid < npts) ? tid : (npts - 1))];
        sidx[tid] = i;
        float mn0 = xmins[2 * k], mn1 = xmins[2 * k + 1];
        float mx0 = xmaxs[2 * k], mx1 = xmaxs[2 * k + 1];
        float c0 = 0.5f * (mn0 + mx0), c1 = 0.5f * (mn1 + mx1);
        float s0 = fmaxf(0.5f * (mx0 - mn0), 1e-9f);
        float s1 = fmaxf(0.5f * (mx1 - mn1), 1e-9f);
        sxn[2 * tid] = (x[2 * i] - c0) / s0;
        sxn[2 * tid + 1] = (x[2 * i + 1] - c1) / s1;
        swn[tid] = g_wn[k][i];
    } else if (tid < 384) {
        int t2 = tid - 128;
        if (t2 < 256) sbias[t2] = b1[k * WD + t2];
    } else {
        int t2 = tid - 384;
        sbias[256 + t2] = b2[k * WD + t2];
        sbias[384 + t2] = b2[k * WD + 128 + t2];
    }
    if (tid < 256) sw3[tid] = W3[k * WD + tid];
    float b3k = b3[k];
    __syncthreads();

    // layer 0: thread = (point-group pg of 32, col-pair c2)
    {
        const float* W0k = W0 + k * 2 * WD;
        int c2 = tid & 127, pg = tid >> 7;
        int v0 = 2 * c2;
        float wa0 = W0k[v0], wb0v = W0k[WD + v0];
        float wa1 = W0k[v0 + 1], wb1v = W0k[WD + v0 + 1];
        float ba = b0[k * WD + v0], bbv = b0[k * WD + v0 + 1];
        __half2* Arow = (__half2*)(A) + c2;
#pragma unroll 4
        for (int pp = 0; pp < 32; ++pp) {
            int p = pg * 32 + pp;
            float xa = sxn[2 * p], xb = sxn[2 * p + 1];
            float u0 = ftanh(fmaf(xa, wa0, fmaf(xb, wb0v, ba)));
            float u1 = ftanh(fmaf(xa, wa1, fmaf(xb, wb1v, bbv)));
            Arow[p * (A_STRIDE / 2)] = __floats2half2_rn(u0, u1);
        }
    }

    // warp grid: 4 n-groups of 64 cols x 4 m-groups of 32 points
    int N0 = (wid & 3) * 64, M0 = (wid >> 2) * 32;
    unsigned baseA = (unsigned)__cvta_generic_to_shared(A);
    unsigned baseW = (unsigned)__cvta_generic_to_shared(Wb);
    // ldmatrix lane geometry
    int l7 = lane & 7, lb3 = (lane >> 3) & 1, lb4 = (lane >> 4) & 1;
    // A: row bit = lb3, k bit = lb4; B: row bit = lb4, k bit = lb3
    unsigned offA_row = (unsigned)((lb3 * 8 + l7) * A_STRIDE + lb4 * 8) * 2u;
    unsigned offB_row = (unsigned)((lb4 * 8 + l7) * W_STRIDE + lb3 * 8) * 2u;

    float acc[2][8][4];

#pragma unroll 1
    for (int cc = 0; cc < 16; ++cc) {
        int layer = cc >> 3, c = cc & 7;
        asm volatile("cp.async.wait_group 2;" ::: "memory");   // chunk cc arrived
        __syncthreads();
        if (cc + 3 < 16) {
            int nx = cc + 3;
            stage_chunk16((const uint4*)(g_WTh +
                          (size_t)(((nx >> 3) * KSUB + k) * 8 + (nx & 7)) * 8192),
                          Wb + (nx & 3) * WBUF_HALVES, tid);
        } else {
            asm volatile("cp.async.commit_group;" ::: "memory");  // empty group
        }
        if (c == 0) {
#pragma unroll
            for (int m = 0; m < 2; ++m)
#pragma unroll
                for (int nt = 0; nt < 8; ++nt)
#pragma unroll
                    for (int r = 0; r < 4; ++r) acc[m][nt][r] = 0.f;
        }
        unsigned wc = baseW + (unsigned)(cc & 3) * WBUF_BYTES;
#pragma unroll
        for (int ks = 0; ks < 2; ++ks) {
            unsigned br[16];
#pragma unroll
            for (int j = 0; j < 4; ++j) {
                unsigned addr = wc + offB_row +
                    (unsigned)((N0 + 16 * j) * W_STRIDE + ks * 16) * 2u;
                LDM_X4(br[4 * j], br[4 * j + 1], br[4 * j + 2], br[4 * j + 3], addr);
            }
            int ka = c * 32 + ks * 16;
#pragma unroll
            for (int m = 0; m < 2; ++m) {
                unsigned a0, a1, a2, a3;
                unsigned addr = baseA + offA_row +
                    (unsigned)((M0 + m * 16) * A_STRIDE + ka) * 2u;
                LDM_X4(a0, a1, a2, a3, addr);
#pragma unroll
                for (int nt = 0; nt < 8; ++nt) {
                    asm volatile(
                        "mma.sync.aligned.m16n8k16.row.col.f32.f16.f16.f32 "
                        "{%0,%1,%2,%3}, {%4,%5,%6,%7}, {%8,%9}, {%0,%1,%2,%3};"
                        : "+f"(acc[m][nt][0]), "+f"(acc[m][nt][1]),
                          "+f"(acc[m][nt][2]), "+f"(acc[m][nt][3])
                        : "r"(a0), "r"(a1), "r"(a2), "r"(a3),
                          "r"(br[2 * nt]), "r"(br[2 * nt + 1]));
                }
            }
        }
        if (c == 7) {   // layer done: bias + tanh -> back into A as fp16
            __syncthreads();
            const float* sb = sbias + layer * 256;
            int g = lane >> 2, t = lane & 3;
#pragma unroll
            for (int m = 0; m < 2; ++m) {
                int r0 = M0 + m * 16;
#pragma unroll
                for (int nt = 0; nt < 8; ++nt) {
                    int cb = N0 + nt * 8 + 2 * t;
                    float bx = sb[cb], by = sb[cb + 1];
                    __half2 v0 = __floats2half2_rn(ftanh(acc[m][nt][0] + bx),
                                                   ftanh(acc[m][nt][1] + by));
                    __half2 v1 = __floats2half2_rn(ftanh(acc[m][nt][2] + bx),
                                                   ftanh(acc[m][nt][3] + by));
                    *(__half2*)(A + (r0 + g) * A_STRIDE + cb) = v0;
                    *(__half2*)(A + (r0 + 8 + g) * A_STRIDE + cb) = v1;
                }
            }
        }
    }
    __syncthreads();

    // final: W3 dot + combine. thread = (point p, quarter s4 of 64 cols)
    {
        int p = tid >> 2, s4 = tid & 3;
        const __half2* Ar = (const __half2*)(A + p * A_STRIDE + s4 * 64);
        const float* w3 = sw3 + s4 * 64;
        float partial = 0.0f;
#pragma unroll 8
        for (int c2 = 0; c2 < 32; ++c2) {
            float2 v = __half22float2(Ar[c2]);
            partial = fmaf(v.x, w3[2 * c2], fmaf(v.y, w3[2 * c2 + 1], partial));
        }
        partial += __shfl_down_sync(0xffffffffu, partial, 2, 4);
        partial += __shfl_down_sync(0xffffffffu, partial, 1, 4);
        if (s4 == 0 && p < npts)
            atomicAdd(out + sidx[p], swn[p] * (partial + b3k));
    }
}

extern "C" void kernel_launch(void* const* d_in, const int* in_sizes, int n_in,
                              void* d_out, int out_size) {
    const float* x     = (const float*)d_in[0];
    const float* W0    = (const float*)d_in[1];
    const float* b0    = (const float*)d_in[2];
    const float* W1    = (const float*)d_in[3];
    const float* b1    = (const float*)d_in[4];
    const float* W2    = (const float*)d_in[5];
    const float* b2    = (const float*)d_in[6];
    const float* W3    = (const float*)d_in[7];
    const float* b3    = (const float*)d_in[8];
    const float* xmins = (const float*)d_in[9];
    const float* xmaxs = (const float*)d_in[10];
    float* out = (float*)d_out;

    cudaFuncSetAttribute(mlp_kernel,
                         cudaFuncAttributeMaxDynamicSharedMemorySize, SMEM_BYTES);

    prep_kernel<<<256, 256>>>(W1, W2);
    window_kernel<<<NPTS / 256, 256>>>(x, xmins, xmaxs, out);
    mlp_kernel<<<dim3(128, KSUB), NTHR, SMEM_BYTES>>>(
        x, W0, b0, b1, b2, W3, b3, xmins, xmaxs, out);
}

// round 16
// speedup vs baseline: 4.9100x; 1.0006x over previous
#include <cuda_runtime.h>
#include <cuda_fp16.h>

#define NPTS 16384
#define KSUB 16
#define WD   256
#define TWF  0.2f
#define PI_F 3.14159265358979f

#define AS1  264    // halves: A0/A1 + l1-ring row stride (33x16B, conflict-free)
#define WS2  40     // halves: l2-ring row stride (5x16B, conflict-free)

// smem byte offsets
#define B_A0   0         // 128*264*2 = 67584
#define B_A1   67584     // 67584
#define B_PR   135168    // 2 * 16896 (l1 ring: 32 rows x 264)
#define B_CR   168960    // 2 * 20480 (l2 ring: 256 rows x 40)
#define B_XN   209920
#define B_WN   210944
#define B_IDX  211456
#define B_BIAS 211968    // 512 f32: b1[256], b2[256]
#define B_W3S  214016    // 256 f32
#define B_SP   215040    // 4 x 128 f32
#define SMEM_BYTES 217088

#define NTHR 512

__device__ int    g_count[KSUB];
__device__ int    g_idx[KSUB][NPTS];
__device__ float  g_wn[KSUB][NPTS];
__device__ __half g_WTh[2 * KSUB * WD * WD];   // [layer][k][chunk8][n256][k32]

__device__ __forceinline__ float ftanh(float x) {
    float e = __expf(-2.0f * x);
    return __fdividef(2.0f, 1.0f + e) - 1.0f;
}
__device__ __forceinline__ void cp16s(unsigned dst, const void* src) {
    asm volatile("cp.async.cg.shared.global [%0], [%1], 16;" :: "r"(dst), "l"(src) : "memory");
}
__device__ __forceinline__ void cpcommit() {
    asm volatile("cp.async.commit_group;" ::: "memory");
}
#define CPWAIT0() asm volatile("cp.async.wait_group 0;" ::: "memory")
#define BARX(id, cnt) asm volatile("bar.sync %0, %1;" :: "r"(id), "r"(cnt) : "memory")
#define LDM_X4(r0, r1, r2, r3, addr) \
    asm volatile("ldmatrix.sync.aligned.m8n8.x4.shared.b16 {%0,%1,%2,%3}, [%4];" \
        : "=r"(r0), "=r"(r1), "=r"(r2), "=r"(r3) : "r"(addr))
#define HMMA(acc, a0, a1, a2, a3, b0, b1) \
    asm volatile("mma.sync.aligned.m16n8k16.row.col.f32.f16.f16.f32 " \
        "{%0,%1,%2,%3}, {%4,%5,%6,%7}, {%8,%9}, {%0,%1,%2,%3};" \
        : "+f"(acc[0]), "+f"(acc[1]), "+f"(acc[2]), "+f"(acc[3]) \
        : "r"(a0), "r"(a1), "r"(a2), "r"(a3), "r"(b0), "r"(b1))

__global__ void prep_kernel(const float* __restrict__ W1, const float* __restrict__ W2) {
    __shared__ __half tile[256][40];
    int b = blockIdx.x;
    int l = b >> 7, ks = (b >> 3) & 15, ch = b & 7;
    const float* src = (l ? W2 : W1) + ks * WD * WD + ch * 32 * WD;
    __half* dst = g_WTh + (size_t)((l * KSUB + ks) * 8 + ch) * 8192;
    int tid = threadIdx.x;
#pragma unroll
    for (int i = 0; i < 32; ++i)
        tile[tid][i] = __float2half_rn(src[i * WD + tid]);
    __syncthreads();
    uint4* gout = (uint4*)dst;
#pragma unroll
    for (int q = 0; q < 4; ++q) {
        int f = q * 256 + tid;
        int v = f >> 2, qq = f & 3;
        gout[f] = *(uint4*)&tile[v][qq * 8];
    }
    if (b == 0 && tid < KSUB) g_count[tid] = 0;
}

__global__ void window_kernel(const float* __restrict__ x,
                              const float* __restrict__ xmins,
                              const float* __restrict__ xmaxs,
                              float* __restrict__ out) {
    int n = blockIdx.x * blockDim.x + threadIdx.x;
    out[n] = 0.0f;
    float x0 = x[2 * n], x1 = x[2 * n + 1];
    float wr[KSUB], s = 0.0f;
#pragma unroll
    for (int k = 0; k < KSUB; ++k) {
        float tl0 = fminf(fmaxf((x0 - (xmins[2 * k] - TWF)) * 2.5f, 0.f), 1.f);
        float tr0 = fminf(fmaxf(((xmaxs[2 * k] + TWF) - x0) * 2.5f, 0.f), 1.f);
        float tl1 = fminf(fmaxf((x1 - (xmins[2 * k + 1] - TWF)) * 2.5f, 0.f), 1.f);
        float tr1 = fminf(fmaxf(((xmaxs[2 * k + 1] + TWF) - x1) * 2.5f, 0.f), 1.f);
        float f0 = 0.25f * (1.f - cosf(PI_F * tl0)) * (1.f - cosf(PI_F * tr0));
        float f1 = 0.25f * (1.f - cosf(PI_F * tl1)) * (1.f - cosf(PI_F * tr1));
        wr[k] = f0 * f1; s += wr[k];
    }
    float inv = 1.0f / (s + 1e-9f);
    int lane = threadIdx.x & 31;
#pragma unroll
    for (int k = 0; k < KSUB; ++k) {
        g_wn[k][n] = wr[k] * inv;
        bool act = (wr[k] > 0.0f);
        unsigned m = __ballot_sync(0xffffffffu, act);
        int base = 0;
        if (lane == 0 && m) base = atomicAdd(&g_count[k], __popc(m));
        base = __shfl_sync(0xffffffffu, base, 0);
        if (act) g_idx[k][base + __popc(m & ((1u << lane) - 1u))] = n;
    }
}

// l1 slice c (32 n-cols x full K=256): gather 8 per-k-chunk blocks -> [32][AS1]
__device__ __forceinline__ void stage_l1(const __half* __restrict__ src,
                                         __half* dst, int t) {
#pragma unroll
    for (int q = 0; q < 4; ++q) {
        int piece = q * 256 + t;
        int ch = piece >> 7, rem = piece & 127;
        int nl = rem >> 2, kq = rem & 3;
        unsigned d = (unsigned)__cvta_generic_to_shared(dst + nl * AS1 + ch * 32 + kq * 8);
        cp16s(d, src + ch * 8192 + nl * 32 + kq * 8);
    }
    cpcommit();
}
// l2 chunk c: dense [256 n][32 k] -> [256 n][WS2]
__device__ __forceinline__ void stage_l2(const __half* __restrict__ src,
                                         __half* dst, int t) {
#pragma unroll
    for (int q = 0; q < 4; ++q) {
        int piece = q * 256 + t;
        int n = piece >> 2, kq = piece & 3;
        unsigned d = (unsigned)__cvta_generic_to_shared(dst + n * WS2 + kq * 8);
        cp16s(d, src + n * 32 + kq * 8);
    }
    cpcommit();
}

__global__ void __launch_bounds__(NTHR, 1)
mlp_kernel(const float* __restrict__ x,
           const float* __restrict__ W0, const float* __restrict__ b0,
           const float* __restrict__ b1, const float* __restrict__ b2,
           const float* __restrict__ W3, const float* __restrict__ b3,
           const float* __restrict__ xmins, const float* __restrict__ xmaxs,
           float* __restrict__ out) {
    extern __shared__ char smc[];
    int k = blockIdx.y, cnt = g_count[k], p0 = blockIdx.x * 128;
    if (p0 >= cnt) return;
    int npts = min(128, cnt - p0);
    int tid = threadIdx.x, wid = tid >> 5, lane = tid & 31;

    __half* A0 = (__half*)(smc + B_A0);
    __half* A1 = (__half*)(smc + B_A1);
    __half* PR = (__half*)(smc + B_PR);
    __half* CR = (__half*)(smc + B_CR);
    float* sxn = (float*)(smc + B_XN);
    float* swn = (float*)(smc + B_WN);
    int* sidx  = (int*)(smc + B_IDX);
    float* sbias = (float*)(smc + B_BIAS);
    float* sw3 = (float*)(smc + B_W3S);
    float* spart = (float*)(smc + B_SP);

    const __half* wl1 = g_WTh + (size_t)k * 65536;
    const __half* wl2 = g_WTh + (size_t)(KSUB + k) * 65536;
    bool isP = (wid < 8);
    int gt = isP ? tid : (tid - 256);

    // prologue: each group stages its chunk 0
    if (isP) stage_l1(wl1, PR, gt);
    else     stage_l2(wl2, CR, gt);

    if (tid < 128) {
        int i = g_idx[k][p0 + ((tid < npts) ? tid : (npts - 1))];
        sidx[tid] = i;
        float mn0 = xmins[2 * k], mn1 = xmins[2 * k + 1];
        float mx0 = xmaxs[2 * k], mx1 = xmaxs[2 * k + 1];
        float c0 = 0.5f * (mn0 + mx0), c1 = 0.5f * (mn1 + mx1);
        float s0 = fmaxf(0.5f * (mx0 - mn0), 1e-9f);
        float s1 = fmaxf(0.5f * (mx1 - mn1), 1e-9f);
        sxn[2 * tid] = (x[2 * i] - c0) / s0;
        sxn[2 * tid + 1] = (x[2 * i + 1] - c1) / s1;
        swn[tid] = g_wn[k][i];
    } else if (tid < 384) {
        int t2 = tid - 128;
        if (t2 < 256) sbias[t2] = b1[k * WD + t2];
    } else {
        int t2 = tid - 384;
        sbias[256 + t2] = b2[k * WD + t2];
        sbias[384 + t2] = b2[k * WD + 128 + t2];
    }
    if (tid < 256) sw3[tid] = W3[k * WD + tid];
    float b3k = b3[k];
    __syncthreads();

    // layer 0 (all warps)
    {
        const float* W0k = W0 + k * 2 * WD;
        int c2 = tid & 127, pg = tid >> 7;
        int v0 = 2 * c2;
        float wa0 = W0k[v0], wb0v = W0k[WD + v0];
        float wa1 = W0k[v0 + 1], wb1v = W0k[WD + v0 + 1];
        float ba = b0[k * WD + v0], bbv = b0[k * WD + v0 + 1];
        __half2* Arow = (__half2*)(A0) + c2;
#pragma unroll 4
        for (int pp = 0; pp < 32; ++pp) {
            int p = pg * 32 + pp;
            float xa = sxn[2 * p], xb = sxn[2 * p + 1];
            float u0 = ftanh(fmaf(xa, wa0, fmaf(xb, wb0v, ba)));
            float u1 = ftanh(fmaf(xa, wa1, fmaf(xb, wb1v, bbv)));
            Arow[p * (AS1 / 2)] = __floats2half2_rn(u0, u1);
        }
    }
    __syncthreads();

    int l7 = lane & 7, lb3 = (lane >> 3) & 1, lb4 = (lane >> 4) & 1;
    int g = lane >> 2, t = lane & 3;
    unsigned baseA0 = (unsigned)__cvta_generic_to_shared(A0);
    unsigned baseA1 = (unsigned)__cvta_generic_to_shared(A1);
    unsigned offA  = (unsigned)((lb3 * 8 + l7) * AS1 + lb4 * 8) * 2u;
    unsigned offB1 = (unsigned)((lb4 * 8 + l7) * AS1 + lb3 * 8) * 2u;
    unsigned offB2 = (unsigned)((lb4 * 8 + l7) * WS2 + lb3 * 8) * 2u;

    if (isP) {
        // ---- producer: layer 1 as 8 N-slices (32 cols x K=256) ----
        int pw = wid;
        unsigned basePR = (unsigned)__cvta_generic_to_shared(PR);
        unsigned aW = baseA0 + offA + (unsigned)(pw * 16 * AS1) * 2u;
#pragma unroll 1
        for (int c = 0; c < 8; ++c) {
            CPWAIT0();                         // my pieces of chunk c landed
            BARX(3, 256);                      // everyone's pieces landed + prev MMA done
            if (c < 7)                         // safe: all P past iter c-1 reads
                stage_l1(wl1 + (c + 1) * 1024, PR + ((c + 1) & 1) * (32 * AS1), gt);
            unsigned pb = basePR + (unsigned)(c & 1) * (32 * AS1 * 2);
            float acc1[4][4];
#pragma unroll
            for (int nt = 0; nt < 4; ++nt)
#pragma unroll
                for (int r = 0; r < 4; ++r) acc1[nt][r] = 0.f;
#pragma unroll
            for (int ks = 0; ks < 16; ++ks) {
                unsigned br[8], a0, a1, a2, a3;
                LDM_X4(br[0], br[1], br[2], br[3], pb + offB1 + (unsigned)(ks * 16) * 2u);
                LDM_X4(br[4], br[5], br[6], br[7], pb + offB1 + (unsigned)(16 * AS1 + ks * 16) * 2u);
                LDM_X4(a0, a1, a2, a3, aW + (unsigned)(ks * 32));
#pragma unroll
                for (int nt = 0; nt < 4; ++nt)
                    HMMA(acc1[nt], a0, a1, a2, a3, br[2 * nt], br[2 * nt + 1]);
            }
#pragma unroll
            for (int nt = 0; nt < 4; ++nt) {
                int cg = c * 32 + nt * 8 + 2 * t;
                float ba = sbias[cg], bb2 = sbias[cg + 1];
                __half2 v0 = __floats2half2_rn(ftanh(acc1[nt][0] + ba), ftanh(acc1[nt][1] + bb2));
                __half2 v1 = __floats2half2_rn(ftanh(acc1[nt][2] + ba), ftanh(acc1[nt][3] + bb2));
                *(__half2*)(A1 + (16 * pw + g) * AS1 + cg) = v0;
                *(__half2*)(A1 + (16 * pw + 8 + g) * AS1 + cg) = v1;
            }
            BARX(1, NTHR);                     // slice c published
        }
    } else {
        // ---- consumer: layer 2, 16 logical chunks (2 N-halves x 8 K-chunks) ----
        int cw = wid - 8, mc = cw & 3, ng = cw >> 2;
        unsigned baseCR = (unsigned)__cvta_generic_to_shared(CR);
        float acc2[2][8][4];
#pragma unroll 1
        for (int cc = 0; cc < 16; ++cc) {
            int nh = cc >> 3, c = cc & 7;
            int colb = nh * 128 + ng * 64;
            CPWAIT0();                          // my pieces of chunk cc landed
            BARX(2, 256);                       // everyone's pieces + prev MMA done
            if (cc < 15)                        // restage cycles chunks 0..7 twice
                stage_l2(wl2 + ((cc + 1) & 7) * 8192, CR + ((cc + 1) & 1) * (256 * WS2), gt);
            if (nh == 0) BARX(1, NTHR);         // slice c of A1 published
            if (c == 0) {
#pragma unroll
                for (int m = 0; m < 2; ++m)
#pragma unroll
                    for (int nt = 0; nt < 8; ++nt)
#pragma unroll
                        for (int r = 0; r < 4; ++r) acc2[m][nt][r] = 0.f;
            }
            unsigned cb = baseCR + (unsigned)(cc & 1) * (256 * WS2 * 2);
#pragma unroll
            for (int ks = 0; ks < 2; ++ks) {
                unsigned br[16];
#pragma unroll
                for (int j = 0; j < 4; ++j)
                    LDM_X4(br[4 * j], br[4 * j + 1], br[4 * j + 2], br[4 * j + 3],
                           cb + offB2 + (unsigned)((colb + j * 16) * WS2 + ks * 16) * 2u);
#pragma unroll
                for (int m = 0; m < 2; ++m) {
                    unsigned a0, a1, a2, a3;
                    LDM_X4(a0, a1, a2, a3, baseA1 + offA +
                           (unsigned)((mc * 32 + m * 16) * AS1 + c * 32 + ks * 16) * 2u);
#pragma unroll
                    for (int nt = 0; nt < 8; ++nt)
                        HMMA(acc2[m][nt], a0, a1, a2, a3, br[2 * nt], br[2 * nt + 1]);
                }
            }
            if (c == 7) {                       // N-half done: tanh + W3 dot
                float rp[4] = {0.f, 0.f, 0.f, 0.f};
#pragma unroll
                for (int m = 0; m < 2; ++m)
#pragma unroll
                    for (int nt = 0; nt < 8; ++nt) {
                        int cg = colb + nt * 8 + 2 * t;
                        float w3a = sw3[cg], w3b = sw3[cg + 1];
                        float ba = sbias[256 + cg], bb2 = sbias[256 + cg + 1];
                        rp[m * 2 + 0] += ftanh(acc2[m][nt][0] + ba) * w3a
                                       + ftanh(acc2[m][nt][1] + bb2) * w3b;
                        rp[m * 2 + 1] += ftanh(acc2[m][nt][2] + ba) * w3a
                                       + ftanh(acc2[m][nt][3] + bb2) * w3b;
                    }
#pragma unroll
                for (int j = 0; j < 4; ++j) {
                    rp[j] += __shfl_down_sync(0xffffffffu, rp[j], 2, 4);
                    rp[j] += __shfl_down_sync(0xffffffffu, rp[j], 1, 4);
                }
                if (t == 0) {
                    int arr = nh * 2 + ng;
                    spart[arr * 128 + mc * 32 + g] = rp[0];
                    spart[arr * 128 + mc * 32 + 8 + g] = rp[1];
                    spart[arr * 128 + mc * 32 + 16 + g] = rp[2];
                    spart[arr * 128 + mc * 32 + 24 + g] = rp[3];
                }
            }
        }
    }
    __syncthreads();

    if (tid < 128 && tid < npts) {
        float v = spart[tid] + spart[128 + tid] + spart[256 + tid] + spart[384 + tid] + b3k;
        atomicAdd(out + sidx[tid], swn[tid] * v);
    }
}

extern "C" void kernel_launch(void* const* d_in, const int* in_sizes, int n_in,
                              void* d_out, int out_size) {
    const float* x     = (const float*)d_in[0];
    const float* W0    = (const float*)d_in[1];
    const float* b0    = (const float*)d_in[2];
    const float* W1    = (const float*)d_in[3];
    const float* b1    = (const float*)d_in[4];
    const float* W2    = (const float*)d_in[5];
    const float* b2    = (const float*)d_in[6];
    const float* W3    = (const float*)d_in[7];
    const float* b3    = (const float*)d_in[8];
    const float* xmins = (const float*)d_in[9];
    const float* xmaxs = (const float*)d_in[10];
    float* out = (float*)d_out;

    cudaFuncSetAttribute(mlp_kernel,
                         cudaFuncAttributeMaxDynamicSharedMemorySize, SMEM_BYTES);

    prep_kernel<<<256, 256>>>(W1, W2);
    window_kernel<<<NPTS / 256, 256>>>(x, xmins, xmaxs, out);
    mlp_kernel<<<dim3(64, KSUB), NTHR, SMEM_BYTES>>>(
        x, W0, b0, b1, b2, W3, b3, xmins, xmaxs, out);
}